// round 10
// baseline (speedup 1.0000x reference)
#include <cuda_runtime.h>
#include <cuda_fp16.h>
#include <cuda_bf16.h>
#include <cstdint>

#define DK 128

// -------- device-global scratch --------
__device__ __align__(128) __half g_ABh[100000 * 256]; // fp16 [node][ A'(=A+b1) | B ]
__device__ __align__(16) unsigned char g_Wsw[65536];  // swizzled bf16 B image [N=256][K=128]

__device__ __forceinline__ uint32_t smem_u32(const void* p) {
    uint32_t a; asm("{ .reg .u64 t; cvta.to.shared.u64 t, %1; cvt.u32.u64 %0, t; }" : "=r"(a) : "l"(p));
    return a;
}
__device__ __forceinline__ uint32_t bf16x2(float lo, float hi) {
    uint32_t r; asm("cvt.rn.bf16x2.f32 %0, %1, %2;" : "=r"(r) : "f"(hi), "f"(lo)); return r;
}
__device__ __forceinline__ uint32_t f16x2(float lo, float hi) {
    __half2 h = __floats2half2_rn(lo, hi); return *(uint32_t*)&h;
}

// ---- L2-policy memory ops: ALL policy ld/st must be 32B on this ptxas ----
__device__ __forceinline__ void ldg_ef_32B(const void* p, unsigned long long u[4]) {
    asm volatile("ld.global.nc.L2::evict_first.v4.b64 {%0,%1,%2,%3}, [%4];"
                 : "=l"(u[0]), "=l"(u[1]), "=l"(u[2]), "=l"(u[3]) : "l"(p));
}
__device__ __forceinline__ void ldg_el_32B(const void* p, unsigned long long u[4]) {
    asm volatile("ld.global.nc.L2::evict_last.v4.b64 {%0,%1,%2,%3}, [%4];"
                 : "=l"(u[0]), "=l"(u[1]), "=l"(u[2]), "=l"(u[3]) : "l"(p));
}
__device__ __forceinline__ void stg_el_32B(void* p, unsigned long long a, unsigned long long b,
                                           unsigned long long c, unsigned long long d) {
    asm volatile("st.global.L2::evict_last.v4.b64 [%0], {%1,%2,%3,%4};"
                 :: "l"(p), "l"(a), "l"(b), "l"(c), "l"(d) : "memory");
}
__device__ __forceinline__ void stg_cs_f(float* p, float v) {
    asm volatile("st.global.cs.f32 [%0], %1;" :: "l"(p), "f"(v) : "memory");
}

// Row layout: 256B per row (128 bf16), 16 chunks of 16B, XOR-swizzled by row%8.
__device__ __forceinline__ uint32_t swz(int row, int kchunk) {
    return (uint32_t)(row * 256 + (((kchunk ^ row) & 7) | (kchunk & 8)) * 16);
}

// smem layout (bytes)
#define SM_B1    0
#define SM_A     1024
#define SM_B     (1024 + 32768)
#define SM_STAGE 1024
#define SMEM_BYTES (1024 + 32768 + 65536)   // 99328

// ---------------------------------------------------------------------------
// Prep: B[n][k] = W1cat[k][n] as bf16, swizzled. Coalesced loads along n.
// ---------------------------------------------------------------------------
__global__ __launch_bounds__(256)
void w_prep_kernel(const float* __restrict__ W1)
{
    int idx = blockIdx.x * 256 + threadIdx.x;
    if (idx >= 16384) return;
    int n  = idx & 255;
    int k2 = (idx >> 8) << 1;
    float w0, w1;
    if (n < 128) {
        w0 = __ldg(W1 + (size_t)k2 * 128 + n);
        w1 = __ldg(W1 + (size_t)(k2 + 1) * 128 + n);
    } else {
        w0 = __ldg(W1 + (size_t)(128 + k2) * 128 + (n - 128));
        w1 = __ldg(W1 + (size_t)(129 + k2) * 128 + (n - 128));
    }
    uint32_t off = swz(n, k2 >> 3) + (k2 & 7) * 2;
    *(uint32_t*)(g_Wsw + off) = bf16x2(w0, w1);
}

// ---------------------------------------------------------------------------
// Phase 1: HMMA GEMM. 512 threads, M-tile 128, N=256.
// X: 32B evict_first loads; AB: 32B evict_last stores (pin in L2 for edge).
// ---------------------------------------------------------------------------
__global__ __launch_bounds__(512, 1)
void gemm_mma_kernel(const float* __restrict__ X, const float* __restrict__ b1, int n_nodes)
{
    extern __shared__ unsigned char smem[];
    const uint32_t sb = smem_u32(smem);
    const int tid  = threadIdx.x;
    const int lane = tid & 31;
    const int wid  = tid >> 5;
    const int m0   = blockIdx.x * 128;

    if (tid < 128) *(float*)(smem + SM_B1 + tid * 4) = __ldg(b1 + tid);

    // B image copy via cp.async (overlaps X convert below)
    #pragma unroll
    for (int t = 0; t < 8; ++t) {
        int i = tid + t * 512;
        uint32_t dst = sb + SM_B + i * 16;
        asm volatile("cp.async.ca.shared.global [%0], [%1], 16;"
                     :: "r"(dst), "l"((const uint4*)g_Wsw + i) : "memory");
    }
    asm volatile("cp.async.commit_group;" ::: "memory");

    // X tile: 32B loads (8 floats = one 16B bf16 swizzle chunk), 2048 chunks.
    #pragma unroll
    for (int t = 0; t < 4; ++t) {
        int i  = tid + t * 512;
        int m  = i >> 4;
        int kc = i & 15;             // 16B chunk index = k8/8
        unsigned long long u[4] = {0ull, 0ull, 0ull, 0ull};
        if (m0 + m < n_nodes)
            ldg_ef_32B(X + (size_t)(m0 + m) * DK + kc * 8, u);
        uint4 pack;
        {
            float2 f0 = *(float2*)&u[0];
            float2 f1 = *(float2*)&u[1];
            float2 f2 = *(float2*)&u[2];
            float2 f3 = *(float2*)&u[3];
            pack.x = bf16x2(f0.x, f0.y);
            pack.y = bf16x2(f1.x, f1.y);
            pack.z = bf16x2(f2.x, f2.y);
            pack.w = bf16x2(f3.x, f3.y);
        }
        *(uint4*)(smem + SM_A + swz(m, kc)) = pack;
    }
    asm volatile("cp.async.wait_all;" ::: "memory");
    __syncthreads();

    const int half = wid >> 3;
    const int m0w  = (wid & 7) * 16;

    const int a_row     = m0w + ((lane >> 3) & 1) * 8 + (lane & 7);
    const int a_koff    = lane >> 4;
    const int b_rowbase = half * 128 + ((lane >> 4) & 1) * 8 + (lane & 7);
    const int b_koff    = (lane >> 3) & 1;

    float acc[16][4];
    #pragma unroll
    for (int nb = 0; nb < 16; ++nb)
        #pragma unroll
        for (int j = 0; j < 4; ++j) acc[nb][j] = 0.f;

    #pragma unroll 1
    for (int ks = 0; ks < 8; ++ks) {
        uint32_t a0, a1, a2, a3;
        uint32_t aaddr = sb + SM_A + swz(a_row, ks * 2 + a_koff);
        asm volatile("ldmatrix.sync.aligned.m8n8.x4.shared.b16 {%0,%1,%2,%3}, [%4];"
                     : "=r"(a0), "=r"(a1), "=r"(a2), "=r"(a3) : "r"(aaddr));

        #pragma unroll
        for (int nb16 = 0; nb16 < 8; ++nb16) {
            uint32_t b0, b1r, b2r, b3r;
            uint32_t baddr = sb + SM_B + swz(b_rowbase + nb16 * 16, ks * 2 + b_koff);
            asm volatile("ldmatrix.sync.aligned.m8n8.x4.shared.b16 {%0,%1,%2,%3}, [%4];"
                         : "=r"(b0), "=r"(b1r), "=r"(b2r), "=r"(b3r) : "r"(baddr));
            asm volatile(
                "mma.sync.aligned.m16n8k16.row.col.f32.bf16.bf16.f32 "
                "{%0,%1,%2,%3}, {%4,%5,%6,%7}, {%8,%9}, {%0,%1,%2,%3};"
                : "+f"(acc[2*nb16][0]), "+f"(acc[2*nb16][1]), "+f"(acc[2*nb16][2]), "+f"(acc[2*nb16][3])
                : "r"(a0), "r"(a1), "r"(a2), "r"(a3), "r"(b0), "r"(b1r));
            asm volatile(
                "mma.sync.aligned.m16n8k16.row.col.f32.bf16.bf16.f32 "
                "{%0,%1,%2,%3}, {%4,%5,%6,%7}, {%8,%9}, {%0,%1,%2,%3};"
                : "+f"(acc[2*nb16+1][0]), "+f"(acc[2*nb16+1][1]), "+f"(acc[2*nb16+1][2]), "+f"(acc[2*nb16+1][3])
                : "r"(a0), "r"(a1), "r"(a2), "r"(a3), "r"(b2r), "r"(b3r));
        }
    }
    __syncthreads();

    {   // Epilogue: +b1 on half 0, fp16 pack, conflict-free staging.
        const int mA = m0w + (lane >> 2);
        const int cq = (lane & 3) * 2;
        #pragma unroll
        for (int nb = 0; nb < 16; ++nb) {
            int n = nb * 8 + cq;
            float add0 = 0.f, add1 = 0.f;
            if (half == 0) {
                float2 bb = *(const float2*)(smem + SM_B1 + n * 4);
                add0 = bb.x; add1 = bb.y;
            }
            uint32_t lo = f16x2(acc[nb][0] + add0, acc[nb][1] + add1);
            uint32_t hi = f16x2(acc[nb][2] + add0, acc[nb][3] + add1);
            uint32_t col = (half * 128 + n) * 2;
            *(uint32_t*)(smem + SM_STAGE + mA * 528 + col)       = lo;
            *(uint32_t*)(smem + SM_STAGE + (mA + 8) * 528 + col) = hi;
        }
    }
    __syncthreads();

    // Coalesced 32B evict_last stores: 128 rows x 512B (2048 chunks).
    unsigned char* outp = (unsigned char*)g_ABh + (size_t)m0 * 512;
    #pragma unroll
    for (int t = 0; t < 4; ++t) {
        int i   = tid + t * 512;
        int row = i >> 4;
        int c8  = i & 15;
        if (m0 + row < n_nodes) {
            const unsigned long long* src =
                (const unsigned long long*)(smem + SM_STAGE + row * 528 + c8 * 32);
            stg_el_32B(outp + (size_t)row * 512 + c8 * 32, src[0], src[1], src[2], src[3]);
        }
    }
}

// ---------------------------------------------------------------------------
// Phase 2: quarter-warp (8 lanes) per edge; 32B evict_last gathers,
// 16-component dots, 3-level shfl reduction, streaming output stores.
// ---------------------------------------------------------------------------
__global__ __launch_bounds__(256)
void edge_kernel(const int* __restrict__ eidx,
                 const float* __restrict__ W2,
                 const float* __restrict__ b2,
                 float* __restrict__ out, int n_edges, int n_nodes)
{
    __shared__ float sres[8][32];

    const int lane = threadIdx.x & 31;
    const int wid  = threadIdx.x >> 5;
    const int base = (blockIdx.x * 8 + wid) * 32;
    if (base >= n_edges) return;

    const int ql = lane & 7;    // components ql*16 .. ql*16+15
    const int qw = lane >> 3;   // edge slot within iteration

    float wd[16];
    #pragma unroll
    for (int t = 0; t < 8; ++t) {
        float4 w = __ldg(((const float4*)W2) + ql * 8 + t);
        wd[2*t]   = w.x - w.y;
        wd[2*t+1] = w.z - w.w;
    }
    const float b2d = __ldg(b2 + 0) - __ldg(b2 + 1);

    int el = base + lane;
    bool valid = el < n_edges;
    int si = valid ? __ldg(eidx + el) : 0;
    int di = valid ? __ldg(eidx + n_edges + el) : 0;
    si = min(max(si, 0), n_nodes - 1);
    di = min(max(di, 0), n_nodes - 1);

    const __half2 z2 = __float2half2_rn(0.f);

    #pragma unroll 4
    for (int i = 0; i < 8; ++i) {
        int s = __shfl_sync(0xffffffffu, si, 4 * i + qw);
        int d = __shfl_sync(0xffffffffu, di, 4 * i + qw);

        unsigned long long av[4], bv[4];
        ldg_el_32B(g_ABh + (size_t)s * 256 + ql * 16, av);
        ldg_el_32B(g_ABh + (size_t)d * 256 + 128 + ql * 16, bv);

        float dlt = 0.f;
        #pragma unroll
        for (int j = 0; j < 4; ++j) {
            __half2 a0 = *(__half2*)&av[j];
            __half2 a1 = *((__half2*)&av[j] + 1);
            __half2 b0 = *(__half2*)&bv[j];
            __half2 b1 = *((__half2*)&bv[j] + 1);
            __half2 h0 = __hmax2(__hadd2(a0, b0), z2);
            __half2 h1 = __hmax2(__hadd2(a1, b1), z2);
            float2 f0 = __half22float2(h0);
            float2 f1 = __half22float2(h1);
            dlt = fmaf(f0.x, wd[4*j+0], dlt);
            dlt = fmaf(f0.y, wd[4*j+1], dlt);
            dlt = fmaf(f1.x, wd[4*j+2], dlt);
            dlt = fmaf(f1.y, wd[4*j+3], dlt);
        }

        #pragma unroll
        for (int o = 4; o; o >>= 1)
            dlt += __shfl_xor_sync(0xffffffffu, dlt, o);

        if (ql == 0) sres[wid][4 * i + qw] = dlt;
    }
    __syncwarp();

    if (valid) {
        float d0 = sres[wid][lane] + b2d;     // = s0 - s1
        float e  = __expf(-d0);
        float c  = 1.f / (1.f + e);
        stg_cs_f(out + el, c);
        stg_cs_f(out + n_edges + el, e * c);
    }
}

extern "C" void kernel_launch(void* const* d_in, const int* in_sizes, int n_in,
                              void* d_out, int out_size)
{
    const float* X    = (const float*)d_in[0];
    const int*   eidx = (const int*)d_in[1];     // int32 on device
    const float* W1   = (const float*)d_in[2];
    const float* b1   = (const float*)d_in[3];
    const float* W2   = (const float*)d_in[4];
    const float* b2   = (const float*)d_in[5];
    float* out = (float*)d_out;

    const int n_nodes = in_sizes[0] / DK;   // 100000
    const int n_edges = in_sizes[1] / 2;    // 640000

    w_prep_kernel<<<64, 256>>>(W1);

    cudaFuncSetAttribute(gemm_mma_kernel, cudaFuncAttributeMaxDynamicSharedMemorySize, SMEM_BYTES);
    int gemm_blocks = (n_nodes + 127) / 128;   // 782
    gemm_mma_kernel<<<gemm_blocks, 512, SMEM_BYTES>>>(X, b1, n_nodes);

    int edge_blocks = (n_edges + 255) / 256;
    edge_kernel<<<edge_blocks, 256>>>(eidx, W2, b2, out, n_edges, n_nodes);
}

// round 11
// speedup vs baseline: 1.2521x; 1.2521x over previous
#include <cuda_runtime.h>
#include <cuda_fp16.h>
#include <cuda_bf16.h>
#include <cstdint>

#define DK 128

// -------- device-global scratch --------
__device__ __align__(128) __half g_ABh[100000 * 256]; // fp16 [node][ A'(=A+b1) | B ]
__device__ __align__(16) unsigned char g_Wsw[65536];  // swizzled bf16 B image [N=256][K=128]

__device__ __forceinline__ uint32_t smem_u32(const void* p) {
    uint32_t a; asm("{ .reg .u64 t; cvta.to.shared.u64 t, %1; cvt.u32.u64 %0, t; }" : "=r"(a) : "l"(p));
    return a;
}
__device__ __forceinline__ uint32_t bf16x2(float lo, float hi) {
    uint32_t r; asm("cvt.rn.bf16x2.f32 %0, %1, %2;" : "=r"(r) : "f"(hi), "f"(lo)); return r;
}
__device__ __forceinline__ uint32_t f16x2(float lo, float hi) {
    __half2 h = __floats2half2_rn(lo, hi); return *(uint32_t*)&h;
}

// Row layout: 256B per row (128 bf16), 16 chunks of 16B, XOR-swizzled by row%8.
__device__ __forceinline__ uint32_t swz(int row, int kchunk) {
    return (uint32_t)(row * 256 + (((kchunk ^ row) & 7) | (kchunk & 8)) * 16);
}

// smem layout (bytes)
#define SM_B1    0                       // 512B
#define SM_A     1024                    // 16 KB: 64 x 128 bf16 swizzled
#define SM_B     (1024 + 16384)          // 64 KB: 256 x 128 bf16 swizzled
#define SM_STAGE (SM_B + 65536)          // 33 KB: 64 rows x 528B
#define SMEM_BYTES (SM_STAGE + 64 * 528) // 116736 (~114 KB) -> 1 CTA/SM

// ---------------------------------------------------------------------------
// Prep: B[n][k] = W1cat[k][n] as bf16, swizzled. Coalesced loads along n.
// ---------------------------------------------------------------------------
__global__ __launch_bounds__(256)
void w_prep_kernel(const float* __restrict__ W1)
{
    int idx = blockIdx.x * 256 + threadIdx.x;
    if (idx >= 16384) return;
    int n  = idx & 255;
    int k2 = (idx >> 8) << 1;
    float w0, w1;
    if (n < 128) {
        w0 = __ldg(W1 + (size_t)k2 * 128 + n);
        w1 = __ldg(W1 + (size_t)(k2 + 1) * 128 + n);
    } else {
        w0 = __ldg(W1 + (size_t)(128 + k2) * 128 + (n - 128));
        w1 = __ldg(W1 + (size_t)(129 + k2) * 128 + (n - 128));
    }
    uint32_t off = swz(n, k2 >> 3) + (k2 & 7) * 2;
    *(uint32_t*)(g_Wsw + off) = bf16x2(w0, w1);
}

// ---------------------------------------------------------------------------
// Phase 1: persistent pipelined HMMA GEMM.
// grid=148, 512 threads, M-tile 64. B loaded ONCE per CTA; X of tile t+1
// prefetched into registers during tile t's mainloop.
// Warp w: M-rows (w&3)*16..+15, N-quarter (w>>2)*64..+63 (8 n-blocks).
// ---------------------------------------------------------------------------
__global__ __launch_bounds__(512, 1)
void gemm_mma_kernel(const float* __restrict__ X, const float* __restrict__ b1,
                     int n_nodes, int ntiles)
{
    extern __shared__ unsigned char smem[];
    const uint32_t sb = smem_u32(smem);
    const int tid  = threadIdx.x;
    const int lane = tid & 31;
    const int wid  = tid >> 5;

    if (tid < 128) *(float*)(smem + SM_B1 + tid * 4) = __ldg(b1 + tid);

    // B image copy once per CTA (cp.async, overlaps first X prefetch)
    #pragma unroll
    for (int t = 0; t < 8; ++t) {
        int i = tid + t * 512;
        uint32_t dst = sb + SM_B + i * 16;
        asm volatile("cp.async.ca.shared.global [%0], [%1], 16;"
                     :: "r"(dst), "l"((const uint4*)g_Wsw + i) : "memory");
    }
    asm volatile("cp.async.commit_group;" ::: "memory");

    int tile = blockIdx.x;
    const int step = gridDim.x;

    // Register prefetch of X tile: 2048 float4 chunks, 4 per thread.
    float4 xv[4];
    {
        int m0 = tile * 64;
        #pragma unroll
        for (int c = 0; c < 4; ++c) {
            int i  = tid + c * 512;
            int m  = i >> 5;
            int k4 = (i & 31) << 2;
            xv[c] = make_float4(0.f, 0.f, 0.f, 0.f);
            if (tile < ntiles && m0 + m < n_nodes)
                xv[c] = __ldg((const float4*)(X + (size_t)(m0 + m) * DK + k4));
        }
    }
    asm volatile("cp.async.wait_all;" ::: "memory");
    __syncthreads();

    const int wm = wid & 3;
    const int wn = wid >> 2;
    const int a_row     = wm * 16 + ((lane >> 3) & 1) * 8 + (lane & 7);
    const int a_koff    = lane >> 4;
    const int b_rowbase = wn * 64 + ((lane >> 4) & 1) * 8 + (lane & 7);
    const int b_koff    = (lane >> 3) & 1;
    const int mA = wm * 16 + (lane >> 2);
    const int cq = (lane & 3) * 2;

    while (tile < ntiles) {
        const int m0 = tile * 64;

        // Convert prefetched X -> bf16 swizzled A smem.
        #pragma unroll
        for (int c = 0; c < 4; ++c) {
            int i  = tid + c * 512;
            int m  = i >> 5;
            int k4 = (i & 31) << 2;
            *(uint2*)(smem + SM_A + swz(m, k4 >> 3) + (k4 & 7) * 2) =
                make_uint2(bf16x2(xv[c].x, xv[c].y), bf16x2(xv[c].z, xv[c].w));
        }
        __syncthreads();

        // Prefetch next tile's X into registers (in flight during mainloop).
        const int next = tile + step;
        {
            int nm0 = next * 64;
            #pragma unroll
            for (int c = 0; c < 4; ++c) {
                int i  = tid + c * 512;
                int m  = i >> 5;
                int k4 = (i & 31) << 2;
                float4 v = make_float4(0.f, 0.f, 0.f, 0.f);
                if (next < ntiles && nm0 + m < n_nodes)
                    v = __ldg((const float4*)(X + (size_t)(nm0 + m) * DK + k4));
                xv[c] = v;
            }
        }

        // Mainloop: 8 k-steps x (1 A-ldsm.x4 + 4 B-ldsm.x4 + 8 mma).
        float acc[8][4];
        #pragma unroll
        for (int nb = 0; nb < 8; ++nb)
            #pragma unroll
            for (int j = 0; j < 4; ++j) acc[nb][j] = 0.f;

        #pragma unroll 1
        for (int ks = 0; ks < 8; ++ks) {
            uint32_t a0, a1, a2, a3;
            uint32_t aaddr = sb + SM_A + swz(a_row, ks * 2 + a_koff);
            asm volatile("ldmatrix.sync.aligned.m8n8.x4.shared.b16 {%0,%1,%2,%3}, [%4];"
                         : "=r"(a0), "=r"(a1), "=r"(a2), "=r"(a3) : "r"(aaddr));
            #pragma unroll
            for (int nq = 0; nq < 4; ++nq) {
                uint32_t b0, b1r, b2r, b3r;
                uint32_t baddr = sb + SM_B + swz(b_rowbase + nq * 16, ks * 2 + b_koff);
                asm volatile("ldmatrix.sync.aligned.m8n8.x4.shared.b16 {%0,%1,%2,%3}, [%4];"
                             : "=r"(b0), "=r"(b1r), "=r"(b2r), "=r"(b3r) : "r"(baddr));
                asm volatile(
                    "mma.sync.aligned.m16n8k16.row.col.f32.bf16.bf16.f32 "
                    "{%0,%1,%2,%3}, {%4,%5,%6,%7}, {%8,%9}, {%0,%1,%2,%3};"
                    : "+f"(acc[2*nq][0]), "+f"(acc[2*nq][1]), "+f"(acc[2*nq][2]), "+f"(acc[2*nq][3])
                    : "r"(a0), "r"(a1), "r"(a2), "r"(a3), "r"(b0), "r"(b1r));
                asm volatile(
                    "mma.sync.aligned.m16n8k16.row.col.f32.bf16.bf16.f32 "
                    "{%0,%1,%2,%3}, {%4,%5,%6,%7}, {%8,%9}, {%0,%1,%2,%3};"
                    : "+f"(acc[2*nq+1][0]), "+f"(acc[2*nq+1][1]), "+f"(acc[2*nq+1][2]), "+f"(acc[2*nq+1][3])
                    : "r"(a0), "r"(a1), "r"(a2), "r"(a3), "r"(b2r), "r"(b3r));
            }
        }
        __syncthreads();

        // Epilogue: +b1 on cols<128, fp16 pack, conflict-free staging.
        #pragma unroll
        for (int nb = 0; nb < 8; ++nb) {
            int c = wn * 64 + nb * 8 + cq;      // col 0..255
            float add0 = 0.f, add1 = 0.f;
            if (c < 128) {
                float2 bb = *(const float2*)(smem + SM_B1 + c * 4);
                add0 = bb.x; add1 = bb.y;
            }
            uint32_t lo = f16x2(acc[nb][0] + add0, acc[nb][1] + add1);
            uint32_t hi = f16x2(acc[nb][2] + add0, acc[nb][3] + add1);
            *(uint32_t*)(smem + SM_STAGE + mA * 528 + c * 2)       = lo;
            *(uint32_t*)(smem + SM_STAGE + (mA + 8) * 528 + c * 2) = hi;
        }
        __syncthreads();

        // Coalesced STG: 64 rows x 512B (2048 uint4, 4 per thread).
        uint4* out4 = (uint4*)(g_ABh) + (size_t)m0 * 32;
        #pragma unroll
        for (int t = 0; t < 4; ++t) {
            int i   = tid + t * 512;
            int row = i >> 5;
            int c4  = i & 31;
            if (m0 + row < n_nodes)
                out4[(size_t)row * 32 + c4] =
                    *(const uint4*)(smem + SM_STAGE + row * 528 + c4 * 16);
        }
        tile = next;
    }
}

// ---------------------------------------------------------------------------
// Phase 2: half-warp per edge (exact R7 version, no L2 policy ops).
// ---------------------------------------------------------------------------
__global__ __launch_bounds__(256)
void edge_kernel(const int* __restrict__ eidx,
                 const float* __restrict__ W2,
                 const float* __restrict__ b2,
                 float* __restrict__ out, int n_edges, int n_nodes)
{
    __shared__ float sres[8][32];

    const int lane = threadIdx.x & 31;
    const int wid  = threadIdx.x >> 5;
    const int base = (blockIdx.x * 8 + wid) * 32;
    if (base >= n_edges) return;

    const int hl = lane & 15;
    const int hw = lane >> 4;

    float wd[8];
    #pragma unroll
    for (int t = 0; t < 4; ++t) {
        float4 w = __ldg(((const float4*)W2) + hl * 4 + t);
        wd[2*t]   = w.x - w.y;
        wd[2*t+1] = w.z - w.w;
    }
    const float b2d = __ldg(b2 + 0) - __ldg(b2 + 1);

    int el = base + lane;
    bool valid = el < n_edges;
    int si = valid ? __ldg(eidx + el) : 0;
    int di = valid ? __ldg(eidx + n_edges + el) : 0;
    si = min(max(si, 0), n_nodes - 1);
    di = min(max(di, 0), n_nodes - 1);

    const __half2 z2 = __float2half2_rn(0.f);

    #pragma unroll 4
    for (int i = 0; i < 16; ++i) {
        int s = __shfl_sync(0xffffffffu, si, 2 * i + hw);
        int d = __shfl_sync(0xffffffffu, di, 2 * i + hw);

        uint4 av = __ldg(((const uint4*)(g_ABh + (size_t)s * 256)) + hl);
        uint4 bv = __ldg(((const uint4*)(g_ABh + (size_t)d * 256 + 128)) + hl);

        __half2 h0 = __hmax2(__hadd2(*(__half2*)&av.x, *(__half2*)&bv.x), z2);
        __half2 h1 = __hmax2(__hadd2(*(__half2*)&av.y, *(__half2*)&bv.y), z2);
        __half2 h2 = __hmax2(__hadd2(*(__half2*)&av.z, *(__half2*)&bv.z), z2);
        __half2 h3 = __hmax2(__hadd2(*(__half2*)&av.w, *(__half2*)&bv.w), z2);

        float2 f0 = __half22float2(h0);
        float2 f1 = __half22float2(h1);
        float2 f2 = __half22float2(h2);
        float2 f3 = __half22float2(h3);

        float dlt = f0.x * wd[0];
        dlt = fmaf(f0.y, wd[1], dlt);
        dlt = fmaf(f1.x, wd[2], dlt);
        dlt = fmaf(f1.y, wd[3], dlt);
        dlt = fmaf(f2.x, wd[4], dlt);
        dlt = fmaf(f2.y, wd[5], dlt);
        dlt = fmaf(f3.x, wd[6], dlt);
        dlt = fmaf(f3.y, wd[7], dlt);

        #pragma unroll
        for (int o = 8; o; o >>= 1)
            dlt += __shfl_xor_sync(0xffffffffu, dlt, o);

        if (hl == 0) sres[wid][2 * i + hw] = dlt;
    }
    __syncwarp();

    if (valid) {
        float d0 = sres[wid][lane] + b2d;     // = s0 - s1
        float e  = __expf(-d0);
        float c  = 1.f / (1.f + e);
        out[el]           = c;
        out[n_edges + el] = e * c;
    }
}

extern "C" void kernel_launch(void* const* d_in, const int* in_sizes, int n_in,
                              void* d_out, int out_size)
{
    const float* X    = (const float*)d_in[0];
    const int*   eidx = (const int*)d_in[1];     // int32 on device
    const float* W1   = (const float*)d_in[2];
    const float* b1   = (const float*)d_in[3];
    const float* W2   = (const float*)d_in[4];
    const float* b2   = (const float*)d_in[5];
    float* out = (float*)d_out;

    const int n_nodes = in_sizes[0] / DK;   // 100000
    const int n_edges = in_sizes[1] / 2;    // 640000

    w_prep_kernel<<<64, 256>>>(W1);

    cudaFuncSetAttribute(gemm_mma_kernel, cudaFuncAttributeMaxDynamicSharedMemorySize, SMEM_BYTES);
    const int ntiles = (n_nodes + 63) / 64;  // 1563
    gemm_mma_kernel<<<148, 512, SMEM_BYTES>>>(X, b1, n_nodes, ntiles);

    int edge_blocks = (n_edges + 255) / 256;
    edge_kernel<<<edge_blocks, 256>>>(eidx, W2, b2, out, n_edges, n_nodes);
}